// round 4
// baseline (speedup 1.0000x reference)
#include <cuda_runtime.h>

#define Bb 8
#define Tt 2048
#define SH 36      // S*H
#define CH 48      // channels in x
#define LDIM 512
#define WTOT 18

// -------- scratch (device globals: no allocation allowed) ----------
__device__ float g_env_mean[Bb * SH];
__device__ float g_gw[Bb * 4 * 9];
__device__ float g_coef[4 * Bb * Tt * 12];   // [i][b][t][12]: a0..a8, mw, pad, pad

// -------- helpers ----------
__device__ __forceinline__ int refl(int t) {
    t = t < 0 ? -t : t;
    return t >= Tt ? (2 * Tt - 2 - t) : t;
}

__device__ __forceinline__ unsigned long long pk2(float a, float b) {
    unsigned long long r;
    asm("mov.b64 %0, {%1, %2};" : "=l"(r) : "f"(a), "f"(b));
    return r;
}
__device__ __forceinline__ void upk2(unsigned long long p, float& a, float& b) {
    asm("mov.b64 {%0, %1}, %2;" : "=f"(a), "=f"(b) : "l"(p));
}
// packed dual-fp32 FMA (sm_100+ PTX)
__device__ __forceinline__ void ffma2(unsigned long long& d,
                                      unsigned long long a, unsigned long long b) {
    asm("fma.rn.f32x2 %0, %1, %2, %0;" : "+l"(d) : "l"(a), "l"(b));
}

// -------- K1: per-batch channel means + gaussian weights ----------
__global__ void k_stats(const float* __restrict__ x) {
    int b = blockIdx.x;
    int c = threadIdx.x;   // 0..47
    int y = threadIdx.y;   // 0..7
    float s = 0.f;
    for (int t = y; t < Tt; t += 8)
        s += x[((size_t)b * Tt + t) * CH + c];
    __shared__ float sh[8][48];
    sh[y][c] = s;
    __syncthreads();
    if (y == 0) {
        float tot = 0.f;
#pragma unroll
        for (int yy = 0; yy < 8; yy++) tot += sh[yy][c];
        float mean = tot * (1.0f / Tt);
        if (c < SH) {
            g_env_mean[b * SH + c] = mean;
        } else if ((c - SH) % 3 == 2) {
            int i = (c - SH) / 3;
            float sig = fmaxf(mean, 0.001f);
            float inv2 = 1.0f / (sig * sig);
            float w[9];
            float wsum = 0.f;
#pragma unroll
            for (int j = 0; j < 9; j++) {
                float k = (float)(j - 4);
                w[j] = expf(-0.5f * k * k * inv2);
                wsum += w[j];
            }
            float inv = 1.0f / wsum;
#pragma unroll
            for (int j = 0; j < 9; j++)
                g_gw[(b * 4 + i) * 9 + j] = w[j] * inv;
        }
    }
}

// -------- K2: per-(i,b,t) blur coefficients ----------
__global__ void k_coef(const float* __restrict__ x) {
    int idx = blockIdx.x * blockDim.x + threadIdx.x;   // i*B*T + b*T + t
    if (idx >= 4 * Bb * Tt) return;
    int t = idx % Tt;
    int bi = idx / Tt;
    int b = bi % Bb;
    int i = bi / Bb;
    float w[9];
#pragma unroll
    for (int j = 0; j < 9; j++) w[j] = g_gw[(b * 4 + i) * 9 + j];
    float mw = 0.f;
    float o[12];
#pragma unroll
    for (int j = 0; j < 9; j++) {
        int tj = refl(t - 4 + j);
        const float* row = x + ((size_t)b * Tt + tj) * CH + SH + 3 * i;
        float mu = row[0], sg = row[1];
        o[j] = w[j] * sg;
        mw = fmaf(w[j], mu, mw);
    }
    o[9] = mw; o[10] = 0.f; o[11] = 0.f;
    float4* dst = (float4*)(g_coef + (size_t)idx * 12);
    dst[0] = make_float4(o[0], o[1], o[2], o[3]);
    dst[1] = make_float4(o[4], o[5], o[6], o[7]);
    dst[2] = make_float4(o[8], o[9], o[10], o[11]);
}

// -------- K3: lats = (env - mean) @ lat, fused mean subtraction ----------
#define TTILE 128
__global__ void __launch_bounds__(128) k_lats(const float* __restrict__ x,
                                              const float* __restrict__ lt,
                                              float* __restrict__ out) {
    const int w = blockIdx.y;        // 0..17
    const int i = w / 6;
    const int bt = blockIdx.x;       // B * (T/TTILE)
    const int b = bt / (Tt / TTILE);
    const int t0 = (bt % (Tt / TTILE)) * TTILE;
    const int tid = threadIdx.x;
    const int l4 = tid * 4;

    // latents for this (w, l4..l4+3) in registers, pre-packed for f32x2
    unsigned long long lp[12][2];
#pragma unroll
    for (int h = 0; h < 12; h++) {
        const float4 v = *(const float4*)(lt + ((size_t)(i * 12 + h) * WTOT + w) * LDIM + l4);
        lp[h][0] = pk2(v.x, v.y);
        lp[h][1] = pk2(v.z, v.w);
    }

    __shared__ float env[TTILE * 12];
    __shared__ float mean[12];
    if (tid < 12) mean[tid] = g_env_mean[b * SH + i * 12 + tid];
    __syncthreads();
    for (int idx = tid; idx < TTILE * 12; idx += 128) {
        int tl = idx / 12, h = idx % 12;
        env[idx] = x[((size_t)b * Tt + t0 + tl) * CH + i * 12 + h] - mean[h];
    }
    __syncthreads();

    float* ob = out + (((size_t)b * Tt + t0) * WTOT + w) * LDIM + l4;
    for (int tl = 0; tl < TTILE; tl++) {
        unsigned long long a0 = 0ULL, a1 = 0ULL;
#pragma unroll
        for (int h = 0; h < 12; h++) {
            float e = env[tl * 12 + h];
            unsigned long long ep = pk2(e, e);
            ffma2(a0, lp[h][0], ep);
            ffma2(a1, lp[h][1], ep);
        }
        float4 r;
        upk2(a0, r.x, r.y);
        upk2(a1, r.z, r.w);
        *(float4*)(ob + (size_t)tl * (WTOT * LDIM)) = r;
    }
}

// -------- K4: noise = mw + sum_j a_j * eps[refl(t-4+j)] ----------
template <int QUADS, int ROWS, int TTn>
__global__ void __launch_bounds__(256) k_noise(const float4* __restrict__ eps,
                                               float4* __restrict__ out,
                                               int ni) {
    const int tid = threadIdx.x;
    const int q = tid % QUADS;
    const int row = tid / QUADS;
    const int tiles = Tt / (ROWS * TTn);
    const int b = blockIdx.x / tiles;
    const int tile = blockIdx.x % tiles;
    const int t0 = tile * ROWS * TTn + row * TTn;

    const float4* ep = eps + (size_t)b * Tt * QUADS;
    const float4* cf = (const float4*)g_coef + ((size_t)(ni * Bb + b) * Tt) * 3;
    float4* ob = out + (size_t)b * Tt * QUADS + q;

    for (int t = t0; t < t0 + TTn; t++) {
        float4 c0 = cf[t * 3 + 0];
        float4 c1 = cf[t * 3 + 1];
        float4 c2 = cf[t * 3 + 2];
        float a[9] = {c0.x, c0.y, c0.z, c0.w, c1.x, c1.y, c1.z, c1.w, c2.x};
        unsigned long long s0 = pk2(c2.y, c2.y);
        unsigned long long s1 = s0;
        if (t >= 4 && t < Tt - 4) {
#pragma unroll
            for (int j = 0; j < 9; j++) {
                const ulonglong2 e = *(const ulonglong2*)(ep + (size_t)(t - 4 + j) * QUADS + q);
                unsigned long long ap = pk2(a[j], a[j]);
                ffma2(s0, e.x, ap);
                ffma2(s1, e.y, ap);
            }
        } else {
#pragma unroll
            for (int j = 0; j < 9; j++) {
                int tj = refl(t - 4 + j);
                const ulonglong2 e = *(const ulonglong2*)(ep + (size_t)tj * QUADS + q);
                unsigned long long ap = pk2(a[j], a[j]);
                ffma2(s0, e.x, ap);
                ffma2(s1, e.y, ap);
            }
        }
        float4 r;
        upk2(s0, r.x, r.y);
        upk2(s1, r.z, r.w);
        ob[(size_t)t * QUADS] = r;
    }
}

// -------- launch ----------
extern "C" void kernel_launch(void* const* d_in, const int* in_sizes, int n_in,
                              void* d_out, int out_size) {
    const float* x  = (const float*)d_in[0];
    const float* lt = (const float*)d_in[1];
    const float4* e0 = (const float4*)d_in[2];
    const float4* e1 = (const float4*)d_in[3];
    const float4* e2 = (const float4*)d_in[4];
    const float4* e3 = (const float4*)d_in[5];
    float* out = (float*)d_out;

    const size_t OFFL = 0;
    const size_t OFF0 = (size_t)Bb * Tt * WTOT * LDIM;     // 150994944
    const size_t OFF1 = OFF0 + (size_t)Bb * Tt * 16;       // + 262144
    const size_t OFF2 = OFF1 + (size_t)Bb * Tt * 64;       // + 1048576
    const size_t OFF3 = OFF2 + (size_t)Bb * Tt * 256;      // + 4194304

    k_stats<<<Bb, dim3(48, 8)>>>(x);
    k_coef<<<(4 * Bb * Tt + 255) / 256, 256>>>(x);

    dim3 lgrid(Bb * (Tt / TTILE), WTOT);
    k_lats<<<lgrid, 128>>>(x, lt, out + OFFL);

    k_noise<4,   64, 32><<<Bb * 1,  256>>>(e0, (float4*)(out + OFF0), 0);
    k_noise<16,  16, 32><<<Bb * 4,  256>>>(e1, (float4*)(out + OFF1), 1);
    k_noise<64,   4, 32><<<Bb * 16, 256>>>(e2, (float4*)(out + OFF2), 2);
    k_noise<256,  1, 32><<<Bb * 64, 256>>>(e3, (float4*)(out + OFF3), 3);
}

// round 5
// speedup vs baseline: 1.6968x; 1.6968x over previous
#include <cuda_runtime.h>

#define Bb 8
#define Tt 2048
#define SH 36      // S*H
#define CH 48      // channels in x
#define LDIM 512
#define WTOT 18
#define TTILE 128

// -------- scratch (device globals: no allocation allowed) ----------
__device__ float g_env_mean[Bb * SH];
__device__ float g_gw[Bb * 4 * 9];
__device__ float g_coef[4 * Bb * Tt * 12];   // [i][b][t][12]: a0..a8, mw, pad, pad

// -------- helpers ----------
__device__ __forceinline__ int refl(int t) {
    t = t < 0 ? -t : t;
    return t >= Tt ? (2 * Tt - 2 - t) : t;
}

__device__ __forceinline__ unsigned long long pk2(float a, float b) {
    unsigned long long r;
    asm("mov.b64 %0, {%1, %2};" : "=l"(r) : "f"(a), "f"(b));
    return r;
}
__device__ __forceinline__ void upk2(unsigned long long p, float& a, float& b) {
    asm("mov.b64 {%0, %1}, %2;" : "=f"(a), "=f"(b) : "l"(p));
}
// packed dual-fp32 FMA (sm_100+ PTX)
__device__ __forceinline__ void ffma2(unsigned long long& d,
                                      unsigned long long a, unsigned long long b) {
    asm("fma.rn.f32x2 %0, %1, %2, %0;" : "+l"(d) : "l"(a), "l"(b));
}

// -------- K1: per-batch channel means + gaussian weights ----------
__global__ void k_stats(const float* __restrict__ x) {
    int b = blockIdx.x;
    int c = threadIdx.x;   // 0..47
    int y = threadIdx.y;   // 0..15
    float s = 0.f;
    for (int t = y; t < Tt; t += 16)
        s += x[((size_t)b * Tt + t) * CH + c];
    __shared__ float sh[16][48];
    sh[y][c] = s;
    __syncthreads();
    if (y == 0) {
        float tot = 0.f;
#pragma unroll
        for (int yy = 0; yy < 16; yy++) tot += sh[yy][c];
        float mean = tot * (1.0f / Tt);
        if (c < SH) {
            g_env_mean[b * SH + c] = mean;
        } else if ((c - SH) % 3 == 2) {
            int i = (c - SH) / 3;
            float sig = fmaxf(mean, 0.001f);
            float inv2 = 1.0f / (sig * sig);
            float w[9];
            float wsum = 0.f;
#pragma unroll
            for (int j = 0; j < 9; j++) {
                float k = (float)(j - 4);
                w[j] = expf(-0.5f * k * k * inv2);
                wsum += w[j];
            }
            float inv = 1.0f / wsum;
#pragma unroll
            for (int j = 0; j < 9; j++)
                g_gw[(b * 4 + i) * 9 + j] = w[j] * inv;
        }
    }
}

// -------- K2: per-(i,b,t) blur coefficients ----------
__global__ void k_coef(const float* __restrict__ x) {
    int idx = blockIdx.x * blockDim.x + threadIdx.x;   // i*B*T + b*T + t
    if (idx >= 4 * Bb * Tt) return;
    int t = idx % Tt;
    int bi = idx / Tt;
    int b = bi % Bb;
    int i = bi / Bb;
    float w[9];
#pragma unroll
    for (int j = 0; j < 9; j++) w[j] = g_gw[(b * 4 + i) * 9 + j];
    float mw = 0.f;
    float o[12];
#pragma unroll
    for (int j = 0; j < 9; j++) {
        int tj = refl(t - 4 + j);
        const float* row = x + ((size_t)b * Tt + tj) * CH + SH + 3 * i;
        float mu = row[0], sg = row[1];
        o[j] = w[j] * sg;
        mw = fmaf(w[j], mu, mw);
    }
    o[9] = mw; o[10] = 0.f; o[11] = 0.f;
    float4* dst = (float4*)(g_coef + (size_t)idx * 12);
    dst[0] = make_float4(o[0], o[1], o[2], o[3]);
    dst[1] = make_float4(o[4], o[5], o[6], o[7]);
    dst[2] = make_float4(o[8], o[9], o[10], o[11]);
}

// -------- lats block body: lats = (env - mean) @ lat ----------
__device__ __forceinline__ void lats_blk(const float* __restrict__ x,
                                         const float* __restrict__ lt,
                                         float* __restrict__ out,
                                         int id, int tid) {
    const int w = id % WTOT;
    const int bt = id / WTOT;
    const int b = bt / (Tt / TTILE);
    const int t0 = (bt % (Tt / TTILE)) * TTILE;
    const int i = w / 6;
    const int l4 = tid * 4;

    unsigned long long lp[12][2];
#pragma unroll
    for (int h = 0; h < 12; h++) {
        const float4 v = *(const float4*)(lt + ((size_t)(i * 12 + h) * WTOT + w) * LDIM + l4);
        lp[h][0] = pk2(v.x, v.y);
        lp[h][1] = pk2(v.z, v.w);
    }

    __shared__ float env[TTILE * 12];
    __shared__ float mean[12];
    if (tid < 12) mean[tid] = g_env_mean[b * SH + i * 12 + tid];
    __syncthreads();
    for (int idx = tid; idx < TTILE * 12; idx += 128) {
        int tl = idx / 12, h = idx % 12;
        env[idx] = x[((size_t)b * Tt + t0 + tl) * CH + i * 12 + h] - mean[h];
    }
    __syncthreads();

    float* ob = out + (((size_t)b * Tt + t0) * WTOT + w) * LDIM + l4;
    for (int tl = 0; tl < TTILE; tl++) {
        unsigned long long a0 = 0ULL, a1 = 0ULL;
#pragma unroll
        for (int h = 0; h < 12; h++) {
            float e = env[tl * 12 + h];
            unsigned long long ep = pk2(e, e);
            ffma2(a0, lp[h][0], ep);
            ffma2(a1, lp[h][1], ep);
        }
        float4 r;
        upk2(a0, r.x, r.y);
        upk2(a1, r.z, r.w);
        *(float4*)(ob + (size_t)tl * (WTOT * LDIM)) = r;
    }
}

// -------- noise block body: out = mw + sum_j a_j * eps[refl(t-4+j)] ----------
template <int QUADS, int QB, int TBLK>
__device__ __forceinline__ void noise_blk(const float4* __restrict__ eps,
                                          float4* __restrict__ out,
                                          int ni, int idx, int tid) {
    constexpr int ROWS = 128 / QB;
    constexpr int TILES = Tt / (ROWS * TBLK);
    constexpr int NSPLIT = QUADS / QB;
    constexpr int PERB = TILES * NSPLIT;

    const int b = idx / PERB;
    const int rem = idx % PERB;
    const int split = rem % NSPLIT;
    const int tile = rem / NSPLIT;
    const int q = split * QB + (tid % QB);
    const int row = tid / QB;
    const int t0 = tile * ROWS * TBLK + row * TBLK;

    const float4* ep = eps + (size_t)b * Tt * QUADS;
    const float4* cf = (const float4*)g_coef + ((size_t)(ni * Bb + b) * Tt) * 3;
    float4* ob = out + (size_t)b * Tt * QUADS + q;

    for (int t = t0; t < t0 + TBLK; t++) {
        float4 c0 = cf[t * 3 + 0];
        float4 c1 = cf[t * 3 + 1];
        float4 c2 = cf[t * 3 + 2];
        float a[9] = {c0.x, c0.y, c0.z, c0.w, c1.x, c1.y, c1.z, c1.w, c2.x};
        unsigned long long s0 = pk2(c2.y, c2.y);
        unsigned long long s1 = s0;
        if (t >= 4 && t < Tt - 4) {
#pragma unroll
            for (int j = 0; j < 9; j++) {
                const ulonglong2 e = *(const ulonglong2*)(ep + (size_t)(t - 4 + j) * QUADS + q);
                unsigned long long ap = pk2(a[j], a[j]);
                ffma2(s0, e.x, ap);
                ffma2(s1, e.y, ap);
            }
        } else {
#pragma unroll
            for (int j = 0; j < 9; j++) {
                int tj = refl(t - 4 + j);
                const ulonglong2 e = *(const ulonglong2*)(ep + (size_t)tj * QUADS + q);
                unsigned long long ap = pk2(a[j], a[j]);
                ffma2(s0, e.x, ap);
                ffma2(s1, e.y, ap);
            }
        }
        float4 r;
        upk2(s0, r.x, r.y);
        upk2(s1, r.z, r.w);
        ob[(size_t)t * QUADS] = r;
    }
}

// -------- mega kernel: lats + all noise, one launch ----------
#define NB_L  (Bb * (Tt / TTILE) * WTOT)   // 2304
#define NB_0  128                          // <4,4,4>    : 8 * 16
#define NB_1  128                          // <16,16,16> : 8 * 16
#define NB_2  256                          // <64,64,32> : 8 * 32
#define NB_3  1024                         // <256,128,32>: 8 * 64 * 2

__global__ void __launch_bounds__(128) k_mega(const float* __restrict__ x,
                                              const float* __restrict__ lt,
                                              const float4* __restrict__ e0,
                                              const float4* __restrict__ e1,
                                              const float4* __restrict__ e2,
                                              const float4* __restrict__ e3,
                                              float* __restrict__ out) {
    const size_t OFF0 = (size_t)Bb * Tt * WTOT * LDIM;
    const size_t OFF1 = OFF0 + (size_t)Bb * Tt * 16;
    const size_t OFF2 = OFF1 + (size_t)Bb * Tt * 64;
    const size_t OFF3 = OFF2 + (size_t)Bb * Tt * 256;

    const int bx = blockIdx.x;
    const int tid = threadIdx.x;

    if (bx < NB_L) {
        lats_blk(x, lt, out, bx, tid);
    } else if (bx < NB_L + NB_0) {
        noise_blk<4, 4, 4>(e0, (float4*)(out + OFF0), 0, bx - NB_L, tid);
    } else if (bx < NB_L + NB_0 + NB_1) {
        noise_blk<16, 16, 16>(e1, (float4*)(out + OFF1), 1, bx - NB_L - NB_0, tid);
    } else if (bx < NB_L + NB_0 + NB_1 + NB_2) {
        noise_blk<64, 64, 32>(e2, (float4*)(out + OFF2), 2, bx - NB_L - NB_0 - NB_1, tid);
    } else {
        noise_blk<256, 128, 32>(e3, (float4*)(out + OFF3), 3,
                                bx - NB_L - NB_0 - NB_1 - NB_2, tid);
    }
}

// -------- launch ----------
extern "C" void kernel_launch(void* const* d_in, const int* in_sizes, int n_in,
                              void* d_out, int out_size) {
    const float* x  = (const float*)d_in[0];
    const float* lt = (const float*)d_in[1];
    const float4* e0 = (const float4*)d_in[2];
    const float4* e1 = (const float4*)d_in[3];
    const float4* e2 = (const float4*)d_in[4];
    const float4* e3 = (const float4*)d_in[5];
    float* out = (float*)d_out;

    k_stats<<<Bb, dim3(48, 16)>>>(x);
    k_coef<<<(4 * Bb * Tt + 255) / 256, 256>>>(x);
    k_mega<<<NB_L + NB_0 + NB_1 + NB_2 + NB_3, 128>>>(x, lt, e0, e1, e2, e3, out);
}

// round 9
// speedup vs baseline: 1.7293x; 1.0192x over previous
#include <cuda_runtime.h>

#define Bb 8
#define Tt 2048
#define SH 36      // S*H
#define CH 48      // channels in x
#define LDIM 512
#define WTOT 18
#define TTILE 128

// -------- scratch (device globals: no allocation allowed) ----------
__device__ float g_part[Bb * 16 * CH];
__device__ float g_env_mean[Bb * SH];
__device__ float g_gw[Bb * 4 * 9];
__device__ float g_coef[4 * Bb * Tt * 12];   // [i][b][t][12]: a0..a8, mw, pad, pad

// -------- helpers ----------
__device__ __forceinline__ int refl(int t) {
    t = t < 0 ? -t : t;
    return t >= Tt ? (2 * Tt - 2 - t) : t;
}

__device__ __forceinline__ unsigned long long pk2(float a, float b) {
    unsigned long long r;
    asm("mov.b64 %0, {%1, %2};" : "=l"(r) : "f"(a), "f"(b));
    return r;
}
__device__ __forceinline__ void upk2(unsigned long long p, float& a, float& b) {
    asm("mov.b64 {%0, %1}, %2;" : "=f"(a), "=f"(b) : "l"(p));
}
// packed dual-fp32 FMA (sm_100+ PTX)
__device__ __forceinline__ void ffma2(unsigned long long& d,
                                      unsigned long long a, unsigned long long b) {
    asm("fma.rn.f32x2 %0, %1, %2, %0;" : "+l"(d) : "l"(a), "l"(b));
}

// -------- stats phase 1: partial channel sums, 16 partials per batch ----------
__global__ void __launch_bounds__(192) k_stats1(const float* __restrict__ x) {
    const int bx = blockIdx.x;          // b*16 + part
    const int b = bx >> 4;
    const int part = bx & 15;
    const int c = threadIdx.x % CH;
    const int y = threadIdx.x / CH;     // 0..3
    float s = 0.f;
    const float* base = x + ((size_t)b * Tt + part * 128) * CH + c;
#pragma unroll 4
    for (int r = 0; r < 32; r++)
        s += base[(size_t)(y + r * 4) * CH];
    __shared__ float sh[4][CH];
    sh[y][c] = s;
    __syncthreads();
    if (y == 0)
        g_part[bx * CH + c] = sh[0][c] + sh[1][c] + sh[2][c] + sh[3][c];
}

// -------- stats phase 2: means + gaussian weights ----------
__global__ void k_stats2() {
    const int b = blockIdx.x;
    const int c = threadIdx.x;
    if (c >= CH) return;
    float tot = 0.f;
#pragma unroll
    for (int p = 0; p < 16; p++)
        tot += g_part[(b * 16 + p) * CH + c];
    float mean = tot * (1.0f / Tt);
    if (c < SH) {
        g_env_mean[b * SH + c] = mean;
    } else if ((c - SH) % 3 == 2) {
        int i = (c - SH) / 3;
        float sig = fmaxf(mean, 0.001f);
        float inv2 = 1.0f / (sig * sig);
        float w[9];
        float wsum = 0.f;
#pragma unroll
        for (int j = 0; j < 9; j++) {
            float k = (float)(j - 4);
            w[j] = expf(-0.5f * k * k * inv2);
            wsum += w[j];
        }
        float inv = 1.0f / wsum;
#pragma unroll
        for (int j = 0; j < 9; j++)
            g_gw[(b * 4 + i) * 9 + j] = w[j] * inv;
    }
}

// -------- K2: per-(i,b,t) blur coefficients ----------
__global__ void k_coef(const float* __restrict__ x) {
    int idx = blockIdx.x * blockDim.x + threadIdx.x;   // i*B*T + b*T + t
    if (idx >= 4 * Bb * Tt) return;
    int t = idx % Tt;
    int bi = idx / Tt;
    int b = bi % Bb;
    int i = bi / Bb;
    float w[9];
#pragma unroll
    for (int j = 0; j < 9; j++) w[j] = g_gw[(b * 4 + i) * 9 + j];
    float mw = 0.f;
    float o[12];
#pragma unroll
    for (int j = 0; j < 9; j++) {
        int tj = refl(t - 4 + j);
        const float* row = x + ((size_t)b * Tt + tj) * CH + SH + 3 * i;
        float mu = row[0], sg = row[1];
        o[j] = w[j] * sg;
        mw = fmaf(w[j], mu, mw);
    }
    o[9] = mw; o[10] = 0.f; o[11] = 0.f;
    float4* dst = (float4*)(g_coef + (size_t)idx * 12);
    dst[0] = make_float4(o[0], o[1], o[2], o[3]);
    dst[1] = make_float4(o[4], o[5], o[6], o[7]);
    dst[2] = make_float4(o[8], o[9], o[10], o[11]);
}

// -------- lats block body: lats = (env - mean) @ lat ----------
__device__ __forceinline__ void lats_blk(const float* __restrict__ x,
                                         const float* __restrict__ lt,
                                         float* __restrict__ out,
                                         int id, int tid) {
    const int w = id % WTOT;
    const int bt = id / WTOT;
    const int b = bt / (Tt / TTILE);
    const int t0 = (bt % (Tt / TTILE)) * TTILE;
    const int i = w / 6;
    const int l4 = tid * 4;

    unsigned long long lp[12][2];
#pragma unroll
    for (int h = 0; h < 12; h++) {
        const float4 v = *(const float4*)(lt + ((size_t)(i * 12 + h) * WTOT + w) * LDIM + l4);
        lp[h][0] = pk2(v.x, v.y);
        lp[h][1] = pk2(v.z, v.w);
    }

    __shared__ float env[TTILE * 12];
    __shared__ float mean[12];
    if (tid < 12) mean[tid] = g_env_mean[b * SH + i * 12 + tid];
    __syncthreads();
    for (int idx = tid; idx < TTILE * 12; idx += 128) {
        int tl = idx / 12, h = idx % 12;
        env[idx] = x[((size_t)b * Tt + t0 + tl) * CH + i * 12 + h] - mean[h];
    }
    __syncthreads();

    float* ob = out + (((size_t)b * Tt + t0) * WTOT + w) * LDIM + l4;
    for (int tl = 0; tl < TTILE; tl++) {
        unsigned long long a0 = 0ULL, a1 = 0ULL;
#pragma unroll
        for (int h = 0; h < 12; h++) {
            float e = env[tl * 12 + h];
            unsigned long long ep = pk2(e, e);
            ffma2(a0, lp[h][0], ep);
            ffma2(a1, lp[h][1], ep);
        }
        float4 r;
        upk2(a0, r.x, r.y);
        upk2(a1, r.z, r.w);
        *(float4*)(ob + (size_t)tl * (WTOT * LDIM)) = r;
    }
}

// -------- noise block body: out = mw + sum_j a_j * eps[refl(t-4+j)] ----------
template <int QUADS, int QB, int TBLK>
__device__ __forceinline__ void noise_blk(const float4* __restrict__ eps,
                                          float4* __restrict__ out,
                                          int ni, int idx, int tid) {
    constexpr int ROWS = 128 / QB;
    constexpr int TILES = Tt / (ROWS * TBLK);
    constexpr int NSPLIT = QUADS / QB;
    constexpr int PERB = TILES * NSPLIT;

    const int b = idx / PERB;
    const int rem = idx % PERB;
    const int split = rem % NSPLIT;
    const int tile = rem / NSPLIT;
    const int q = split * QB + (tid % QB);
    const int row = tid / QB;
    const int t0 = tile * ROWS * TBLK + row * TBLK;

    const float4* ep = eps + (size_t)b * Tt * QUADS;
    const float4* cf = (const float4*)g_coef + ((size_t)(ni * Bb + b) * Tt) * 3;
    float4* ob = out + (size_t)b * Tt * QUADS + q;

    for (int t = t0; t < t0 + TBLK; t++) {
        float4 c0 = cf[t * 3 + 0];
        float4 c1 = cf[t * 3 + 1];
        float4 c2 = cf[t * 3 + 2];
        float a[9] = {c0.x, c0.y, c0.z, c0.w, c1.x, c1.y, c1.z, c1.w, c2.x};
        unsigned long long s0 = pk2(c2.y, c2.y);
        unsigned long long s1 = s0;
        if (t >= 4 && t < Tt - 4) {
#pragma unroll
            for (int j = 0; j < 9; j++) {
                const ulonglong2 e = *(const ulonglong2*)(ep + (size_t)(t - 4 + j) * QUADS + q);
                unsigned long long ap = pk2(a[j], a[j]);
                ffma2(s0, e.x, ap);
                ffma2(s1, e.y, ap);
            }
        } else {
#pragma unroll
            for (int j = 0; j < 9; j++) {
                int tj = refl(t - 4 + j);
                const ulonglong2 e = *(const ulonglong2*)(ep + (size_t)tj * QUADS + q);
                unsigned long long ap = pk2(a[j], a[j]);
                ffma2(s0, e.x, ap);
                ffma2(s1, e.y, ap);
            }
        }
        float4 r;
        upk2(s0, r.x, r.y);
        upk2(s1, r.z, r.w);
        ob[(size_t)t * QUADS] = r;
    }
}

// -------- mega kernel: lats + all noise, one launch ----------
#define NB_L  (Bb * (Tt / TTILE) * WTOT)   // 2304
#define NB_0  128                          // <4,4,4>    : 8 * 16
#define NB_1  128                          // <16,16,16> : 8 * 16
#define NB_2  256                          // <64,64,32> : 8 * 32
#define NB_3  1024                         // <256,128,32>: 8 * 128

__global__ void __launch_bounds__(128) k_mega(const float* __restrict__ x,
                                              const float* __restrict__ lt,
                                              const float4* __restrict__ e0,
                                              const float4* __restrict__ e1,
                                              const float4* __restrict__ e2,
                                              const float4* __restrict__ e3,
                                              float* __restrict__ out) {
    const size_t OFF0 = (size_t)Bb * Tt * WTOT * LDIM;
    const size_t OFF1 = OFF0 + (size_t)Bb * Tt * 16;
    const size_t OFF2 = OFF1 + (size_t)Bb * Tt * 64;
    const size_t OFF3 = OFF2 + (size_t)Bb * Tt * 256;

    const int bx = blockIdx.x;
    const int tid = threadIdx.x;

    if (bx < NB_L) {
        lats_blk(x, lt, out, bx, tid);
    } else if (bx < NB_L + NB_0) {
        noise_blk<4, 4, 4>(e0, (float4*)(out + OFF0), 0, bx - NB_L, tid);
    } else if (bx < NB_L + NB_0 + NB_1) {
        noise_blk<16, 16, 16>(e1, (float4*)(out + OFF1), 1, bx - NB_L - NB_0, tid);
    } else if (bx < NB_L + NB_0 + NB_1 + NB_2) {
        noise_blk<64, 64, 32>(e2, (float4*)(out + OFF2), 2, bx - NB_L - NB_0 - NB_1, tid);
    } else {
        noise_blk<256, 128, 32>(e3, (float4*)(out + OFF3), 3,
                                bx - NB_L - NB_0 - NB_1 - NB_2, tid);
    }
}

// -------- launch ----------
extern "C" void kernel_launch(void* const* d_in, const int* in_sizes, int n_in,
                              void* d_out, int out_size) {
    const float* x  = (const float*)d_in[0];
    const float* lt = (const float*)d_in[1];
    const float4* e0 = (const float4*)d_in[2];
    const float4* e1 = (const float4*)d_in[3];
    const float4* e2 = (const float4*)d_in[4];
    const float4* e3 = (const float4*)d_in[5];
    float* out = (float*)d_out;

    k_stats1<<<Bb * 16, 192>>>(x);
    k_stats2<<<Bb, 64>>>();
    k_coef<<<(4 * Bb * Tt + 255) / 256, 256>>>(x);
    k_mega<<<NB_L + NB_0 + NB_1 + NB_2 + NB_3, 128>>>(x, lt, e0, e1, e2, e3, out);
}